// round 14
// baseline (speedup 1.0000x reference)
#include <cuda_runtime.h>

#define NB 1024
#define PIX 784
#define ZDIM 848

__device__ float z_buf[NB * ZDIM];
__device__ float g_part[512 * 256];   // mlp pass1 partials

// ---------------- packed f32x2 helpers ----------------
__device__ __forceinline__ void lds_v2u64(unsigned long long &a, unsigned long long &b,
                                          unsigned saddr) {
    asm volatile("ld.shared.v2.u64 {%0,%1},[%2];" : "=l"(a), "=l"(b) : "r"(saddr));
}
__device__ __forceinline__ unsigned long long addf2(unsigned long long a,
                                                    unsigned long long b) {
    unsigned long long r;
    asm("add.rn.f32x2 %0,%1,%2;" : "=l"(r) : "l"(a), "l"(b));
    return r;
}
__device__ __forceinline__ void upk2(float &lo, float &hi, unsigned long long v) {
    asm("mov.b64 {%0,%1},%2;" : "=f"(lo), "=f"(hi) : "l"(v));
}

// ---------------------------------------------------------------------------
// Dummy kernel: shifts ncu's -s 5 -c 1 capture onto fused_kernel
// (pattern [dummy, fused, mlp1, mlp2] -> launch idx 5 == fused).
// ---------------------------------------------------------------------------
__global__ void dummy_kernel() {}

// ---------------------------------------------------------------------------
// Fused kernel, grid 4096: CTA (b, q) = conv quarter-tile; q==0 CTAs also run
// the TDA branch for sample b after the conv phases (smem overlaid on xs).
// ---------------------------------------------------------------------------
#define XS_FL   (11 * 32)
#define H1_FL   (9 * 30 * 36)
#define G_FL    (196 * 36)
#define CSMEM_FLOATS (XS_FL + H1_FL + G_FL)

__global__ void __launch_bounds__(288, 3) fused_kernel(
    const float* __restrict__ x,
    const float* __restrict__ w1, const float* __restrict__ b1,
    const float* __restrict__ w2, const float* __restrict__ b2,
    const float* __restrict__ dtm1, const float* __restrict__ dtm2,
    const float* __restrict__ g1w, const float* __restrict__ g1b,
    const float* __restrict__ g2w, const float* __restrict__ g2b)
{
    extern __shared__ float smem[];
    int tid = threadIdx.x;
    int lane = tid & 31, wid = tid >> 5;

    // =================== CONV PATH ===================
    float* xs = smem;                 // 11 rows x 32 (col idx = gc+1)
    float* h1 = smem + XS_FL;         // [lr 0..8][cp 0..29][c], stride 36
    float* Gs = h1 + H1_FL;           // [p 0..195][c], stride 36

    int b = blockIdx.x >> 2;
    int q = blockIdx.x & 3;
    int base = 7 * q;                 // output row base: 0,7,14,21

    for (int i = tid; i < XS_FL; i += 288) {
        int r = i >> 5, c = i & 31;
        int gr = base - 2 + r, gc = c - 1;
        float v = 0.0f;
        if (gr >= 0 && gr < 28 && gc >= 0 && gc < 28)
            v = x[b * 784 + gr * 28 + gc];
        xs[i] = v;
    }
    for (int i = tid; i < 9 * 2 * 32; i += 288) {
        int lr = i >> 6;
        int cp = ((i >> 5) & 1) ? 29 : 0;
        int c = i & 31;
        h1[(lr * 30 + cp) * 36 + c] = 0.0f;
    }
    __syncthreads();

    // ---- conv1: lane = channel, warp = h1 local row (9 warps, 9 rows)
    {
        int c = lane;
        float wk[9];
        #pragma unroll
        for (int k = 0; k < 9; k++) wk[k] = w1[k * 32 + c];
        float bc = b1[c];

        int lr = wid;                        // 0..8
        int gr = base - 1 + lr;
        float* hrow = h1 + (lr * 30 + 1) * 36 + c;
        if (gr < 0 || gr >= 28) {
            #pragma unroll
            for (int col = 0; col < 28; col++) hrow[col * 36] = 0.0f;
        } else {
            const float* xr = xs + lr * 32;  // x rows lr, lr+1, lr+2
            float a0 = xr[0],   b0 = xr[1];
            float a1v = xr[32], b1v = xr[33];
            float a2v = xr[64], b2v = xr[65];
            #pragma unroll
            for (int col = 0; col < 28; col++) {
                float c0  = xr[col + 2];
                float c1v = xr[32 + col + 2];
                float c2v = xr[64 + col + 2];
                float t0 = bc;
                t0 += a0  * wk[0]; t0 += b0  * wk[1]; t0 += c0  * wk[2];
                float t1 = a1v * wk[3];
                t1 += b1v * wk[4]; t1 += c1v * wk[5];
                float t2 = a2v * wk[6];
                t2 += b2v * wk[7]; t2 += c2v * wk[8];
                hrow[col * 36] = fmaxf((t0 + t1) + t2, 0.0f);
                a0 = b0;   b0 = c0;
                a1v = b1v; b1v = c1v;
                a2v = b2v; b2v = c2v;
            }
        }
    }
    __syncthreads();

    // ---- G-pass: lane = channel, warp = output row r (warps 0..6)
    if (wid < 7) {
        int c = lane, r = wid;
        float wk[9];
        #pragma unroll
        for (int k = 0; k < 9; k++) wk[k] = w2[k * 32 + c];
        const float* h0 = h1 + ((r    ) * 30) * 36 + c;
        const float* hm = h1 + ((r + 1) * 30) * 36 + c;
        const float* h2 = h1 + ((r + 2) * 30) * 36 + c;
        float a0 = h0[0],  b0 = h0[36];
        float a1 = hm[0],  b1v = hm[36];
        float a2 = h2[0],  b2v = h2[36];
        float* grow = Gs + r * 28 * 36 + c;
        #pragma unroll
        for (int col = 0; col < 28; col++) {
            float c0 = h0[(col + 2) * 36];
            float c1 = hm[(col + 2) * 36];
            float c2 = h2[(col + 2) * 36];
            float t0 = a0  * wk[0];
            t0 += b0  * wk[1]; t0 += c0 * wk[2];
            float t1 = a1  * wk[3];
            t1 += b1v * wk[4]; t1 += c1 * wk[5];
            float t2 = a2  * wk[6];
            t2 += b2v * wk[7]; t2 += c2 * wk[8];
            grow[col * 36] = (t0 + t1) + t2;
            a0 = b0;   b0 = c0;
            a1 = b1v;  b1v = c1;
            a2 = b2v;  b2v = c2;
        }
    }
    __syncthreads();

    // ---- sum-pass: thread = pixel p (0..195)
    if (tid < 196) {
        unsigned saddr = (unsigned)__cvta_generic_to_shared(Gs + tid * 36);
        unsigned long long s0, s1, s2, s3, s4, s5, s6, s7;
        {
            unsigned long long d0, d1, d2, d3;
            lds_v2u64(d0, d1, saddr);
            lds_v2u64(d2, d3, saddr + 16);
            s0 = d0; s1 = d1; s2 = d2; s3 = d3;
            lds_v2u64(d0, d1, saddr + 32);
            lds_v2u64(d2, d3, saddr + 48);
            s4 = d0; s5 = d1; s6 = d2; s7 = d3;
            lds_v2u64(d0, d1, saddr + 64);
            lds_v2u64(d2, d3, saddr + 80);
            s0 = addf2(s0, d0); s1 = addf2(s1, d1);
            s2 = addf2(s2, d2); s3 = addf2(s3, d3);
            lds_v2u64(d0, d1, saddr + 96);
            lds_v2u64(d2, d3, saddr + 112);
            s4 = addf2(s4, d0); s5 = addf2(s5, d1);
            s6 = addf2(s6, d2); s7 = addf2(s7, d3);
        }
        s0 = addf2(s0, s4); s1 = addf2(s1, s5);
        s2 = addf2(s2, s6); s3 = addf2(s3, s7);
        s0 = addf2(s0, s2); s1 = addf2(s1, s3);
        s0 = addf2(s0, s1);
        float lo, hi;
        upk2(lo, hi, s0);
        float acc = lo + hi + b2[0];
        z_buf[b * ZDIM + base * 28 + tid] = fmaxf(acc, 0.0f);
    }

    if (q != 0) return;

    // =================== TDA PATH (quarter-0 CTAs only) ===================
    __syncthreads();                  // xs region now dead -> reuse
    {
        float* red  = xs;             // 9 warps x 6
        float* fin  = xs + 64;        // 6
        float* lam1 = xs + 80;        // 64
        float* lam2 = xs + 144;       // 64

        const float4* v1 = (const float4*)(dtm1 + b * PIX);
        const float4* v2 = (const float4*)(dtm2 + b * PIX);

        float mx1 = -1e30f, a1 = 1e30f, a2 = 1e30f;
        float mx2 = -1e30f, c1 = 1e30f, c2 = 1e30f;
        if (tid < 196) {
            float4 u4 = v1[tid];
            float4 w4 = v2[tid];
            #pragma unroll
            for (int j = 0; j < 4; j++) {
                float u = (j == 0) ? u4.x : (j == 1) ? u4.y : (j == 2) ? u4.z : u4.w;
                mx1 = fmaxf(mx1, u);
                if (u < a1) { a2 = a1; a1 = u; } else if (u < a2) a2 = u;
                float w = (j == 0) ? w4.x : (j == 1) ? w4.y : (j == 2) ? w4.z : w4.w;
                mx2 = fmaxf(mx2, w);
                if (w < c1) { c2 = c1; c1 = w; } else if (w < c2) c2 = w;
            }
        }
        #pragma unroll
        for (int off = 16; off; off >>= 1) {
            mx1 = fmaxf(mx1, __shfl_xor_sync(~0u, mx1, off));
            float o1 = __shfl_xor_sync(~0u, a1, off);
            float o2 = __shfl_xor_sync(~0u, a2, off);
            float n1 = fminf(a1, o1);
            float n2 = fminf(fmaxf(a1, o1), fminf(a2, o2));
            a1 = n1; a2 = n2;
            mx2 = fmaxf(mx2, __shfl_xor_sync(~0u, mx2, off));
            float p1 = __shfl_xor_sync(~0u, c1, off);
            float p2 = __shfl_xor_sync(~0u, c2, off);
            float q1 = fminf(c1, p1);
            float q2 = fminf(fmaxf(c1, p1), fminf(c2, p2));
            c1 = q1; c2 = q2;
        }
        if (lane == 0) {
            red[wid * 6 + 0] = mx1; red[wid * 6 + 1] = a1; red[wid * 6 + 2] = a2;
            red[wid * 6 + 3] = mx2; red[wid * 6 + 4] = c1; red[wid * 6 + 5] = c2;
        }
        __syncthreads();
        if (tid == 0) {
            float M1 = red[0], A1 = red[1], A2 = red[2];
            float M2 = red[3], C1 = red[4], C2 = red[5];
            #pragma unroll
            for (int w = 1; w < 9; w++) {
                M1 = fmaxf(M1, red[w * 6 + 0]);
                float o1 = red[w * 6 + 1], o2 = red[w * 6 + 2];
                float n1 = fminf(A1, o1);
                float n2 = fminf(fmaxf(A1, o1), fminf(A2, o2));
                A1 = n1; A2 = n2;
                M2 = fmaxf(M2, red[w * 6 + 3]);
                float p1 = red[w * 6 + 4], p2 = red[w * 6 + 5];
                float q1 = fminf(C1, p1);
                float q2 = fminf(fmaxf(C1, p1), fminf(C2, p2));
                C1 = q1; C2 = q2;
            }
            fin[0] = M1; fin[1] = A1; fin[2] = A2;
            fin[3] = M2; fin[4] = C1; fin[5] = C2;
        }
        __syncthreads();

        if (tid < 128) {
            int k = (tid >> 5) & 1, t = tid & 31;
            if (tid < 64) {
                float tv1 = 0.01f + (float)t * (0.28f / 31.0f);
                float m1 = k ? fin[2] : fin[1];
                lam1[tid] = fmaxf(0.0f, fminf(tv1 - m1, fin[0] - tv1));
            } else {
                float tv2 = 0.05f + (float)t * (0.25f / 31.0f);
                float m2 = k ? fin[5] : fin[4];
                lam2[tid - 64] = fmaxf(0.0f, fminf(tv2 - m2, fin[3] - tv2));
            }
        }
        __syncthreads();

        if (tid < 32) {
            float acc = g1b[tid];
            #pragma unroll
            for (int i = 0; i < 64; i++) acc += lam1[i] * g1w[i * 32 + tid];
            z_buf[b * ZDIM + 784 + tid] = fmaxf(acc, 0.0f);
        } else if (tid < 64) {
            int j = tid - 32;
            float acc = g2b[j];
            #pragma unroll
            for (int i = 0; i < 64; i++) acc += lam2[i] * g2w[i * 32 + j];
            z_buf[b * ZDIM + 816 + j] = fmaxf(acc, 0.0f);
        }
    }
}

// ---------------------------------------------------------------------------
// MLP pass1: K-split GEMM. Block (g, h): sample group g (4 samples), K-half h
// (rows [424h, 424h+424)). 256 threads = 8 row-segments x 32 col-pairs.
// Thread: 53 rows x 2 cols x 4 samples; depth-4 weight prefetch ring.
// Writes raw partials to g_part[bx][s*64+c].
// ---------------------------------------------------------------------------
__global__ void __launch_bounds__(256) mlp_pass1(
    const float* __restrict__ fc1w)
{
    __shared__ float zt[424 * 4];        // [local_row][s]
    __shared__ float part[256 * 9];      // [(s*64+c)*9 + seg]

    int tid = threadIdx.x;
    int g = blockIdx.x >> 1, h = blockIdx.x & 1;
    int bbase = g * 4;
    int rowbase = 424 * h;

    // load z rows [rowbase, rowbase+424) for 4 samples, transposed
    {
        for (int i = tid; i < 4 * 106; i += 256) {
            int s = i / 106;
            int r4 = i - s * 106;
            float4 v = *(const float4*)(z_buf + (size_t)(bbase + s) * ZDIM
                                        + rowbase + r4 * 4);
            int r = r4 * 4;
            zt[(r + 0) * 4 + s] = v.x;
            zt[(r + 1) * 4 + s] = v.y;
            zt[(r + 2) * 4 + s] = v.z;
            zt[(r + 3) * 4 + s] = v.w;
        }
    }
    __syncthreads();

    {
        int seg = tid >> 5, cg = tid & 31;       // 8 segs x 32 col-pairs
        int r0 = seg * 53;                        // local row base
        const float2* wrow = (const float2*)fc1w + cg;   // + row*32

        float acc[4][2];
        #pragma unroll
        for (int s = 0; s < 4; s++) { acc[s][0] = 0.0f; acc[s][1] = 0.0f; }

        float2 wb[4];
        #pragma unroll
        for (int gg = 0; gg < 4; gg++)
            wb[gg] = wrow[(rowbase + r0 + gg) * 32];
        float2 wlast = wrow[(rowbase + r0 + 52) * 32];

        #pragma unroll 1
        for (int it = 0; it < 12; it++) {          // local rows r0 .. r0+47
            int rb = r0 + it * 4;
            #pragma unroll
            for (int gg = 0; gg < 4; gg++) {
                float2 w = wb[gg];
                wb[gg] = wrow[(rowbase + rb + gg + 4) * 32];
                float4 zv = *(const float4*)(zt + (rb + gg) * 4);
                acc[0][0] += zv.x * w.x; acc[0][1] += zv.x * w.y;
                acc[1][0] += zv.y * w.x; acc[1][1] += zv.y * w.y;
                acc[2][0] += zv.z * w.x; acc[2][1] += zv.z * w.y;
                acc[3][0] += zv.w * w.x; acc[3][1] += zv.w * w.y;
            }
        }
        #pragma unroll
        for (int gg = 0; gg < 5; gg++) {           // rows r0+48..r0+52
            float2 w = (gg < 4) ? wb[gg] : wlast;
            float4 zv = *(const float4*)(zt + (r0 + 48 + gg) * 4);
            acc[0][0] += zv.x * w.x; acc[0][1] += zv.x * w.y;
            acc[1][0] += zv.y * w.x; acc[1][1] += zv.y * w.y;
            acc[2][0] += zv.z * w.x; acc[2][1] += zv.z * w.y;
            acc[3][0] += zv.w * w.x; acc[3][1] += zv.w * w.y;
        }

        #pragma unroll
        for (int s = 0; s < 4; s++) {
            part[(s * 64 + cg * 2 + 0) * 9 + seg] = acc[s][0];
            part[(s * 64 + cg * 2 + 1) * 9 + seg] = acc[s][1];
        }
    }
    __syncthreads();

    // reduce 8 segments, write raw partial to global
    {
        const float* pp = part + tid * 9;
        float s0 = pp[0] + pp[1], s1 = pp[2] + pp[3];
        float s2 = pp[4] + pp[5], s3 = pp[6] + pp[7];
        g_part[blockIdx.x * 256 + tid] = (s0 + s1) + (s2 + s3);
    }
}

// ---------------------------------------------------------------------------
// MLP pass2: combine halves + bias + relu + fc2. Grid 256 (one sample group).
// ---------------------------------------------------------------------------
__global__ void __launch_bounds__(256) mlp_pass2(
    const float* __restrict__ fc1b,
    const float* __restrict__ fc2w, const float* __restrict__ fc2b,
    float* __restrict__ out)
{
    __shared__ float ys[4 * 68];
    int tid = threadIdx.x;
    int g = blockIdx.x;
    int bbase = g * 4;

    {
        float v = g_part[(2 * g) * 256 + tid] + g_part[(2 * g + 1) * 256 + tid];
        int s = tid >> 6, c = tid & 63;
        ys[s * 68 + c] = fmaxf(v + fc1b[c], 0.0f);
    }
    __syncthreads();

    if (tid < 40) {
        int s = tid / 10, k = tid - s * 10;
        float acc = fc2b[k];
        #pragma unroll
        for (int jj = 0; jj < 64; jj++)
            acc += ys[s * 68 + jj] * fc2w[jj * 10 + k];
        out[(bbase + s) * 10 + k] = acc;
    }
}

// ---------------------------------------------------------------------------
extern "C" void kernel_launch(void* const* d_in, const int* in_sizes, int n_in,
                              void* d_out, int out_size)
{
    const float* x    = (const float*)d_in[0];
    const float* dtm1 = (const float*)d_in[1];
    const float* dtm2 = (const float*)d_in[2];
    const float* w1   = (const float*)d_in[3];
    const float* b1   = (const float*)d_in[4];
    const float* w2   = (const float*)d_in[5];
    const float* b2   = (const float*)d_in[6];
    const float* g1w  = (const float*)d_in[7];
    const float* g1b  = (const float*)d_in[8];
    const float* g2w  = (const float*)d_in[9];
    const float* g2b  = (const float*)d_in[10];
    const float* fc1w = (const float*)d_in[11];
    const float* fc1b = (const float*)d_in[12];
    const float* fc2w = (const float*)d_in[13];
    const float* fc2b = (const float*)d_in[14];
    float* out = (float*)d_out;

    cudaFuncSetAttribute(fused_kernel, cudaFuncAttributeMaxDynamicSharedMemorySize,
                         CSMEM_FLOATS * (int)sizeof(float));
    cudaFuncSetAttribute(fused_kernel, cudaFuncAttributePreferredSharedMemoryCarveout,
                         100);

    dummy_kernel<<<1, 1>>>();
    fused_kernel<<<4096, 288, CSMEM_FLOATS * sizeof(float)>>>(
        x, w1, b1, w2, b2, dtm1, dtm2, g1w, g1b, g2w, g2b);
    mlp_pass1<<<512, 256>>>(fc1w);
    mlp_pass2<<<256, 256>>>(fc1b, fc2w, fc2b, out);
}

// round 15
// speedup vs baseline: 1.0206x; 1.0206x over previous
#include <cuda_runtime.h>

#define NB 1024
#define PIX 784
#define ZDIM 848

__device__ float z_buf[NB * ZDIM];

// ---------------------------------------------------------------------------
// Fused kernel. Blocks [0,4096): conv quarter-tiles. Blocks [4096,5120): TDA.
//   R15: G-pass channel sum done as warp shfl butterfly -> Gs buffer, the
//   sum-pass, and one barrier deleted. smem 68.5KB -> 40.3KB; lb(288,4)
//   caps regs at 56 -> 4 CTAs/SM (waves 11.5 -> 8.6).
// ---------------------------------------------------------------------------
#define XS_FL   (11 * 32)
#define H1_FL   (9 * 30 * 36)
#define CSMEM_FLOATS (XS_FL + H1_FL)

__global__ void __launch_bounds__(288, 4) fused_kernel(
    const float* __restrict__ x,
    const float* __restrict__ w1, const float* __restrict__ b1,
    const float* __restrict__ w2, const float* __restrict__ b2,
    const float* __restrict__ dtm1, const float* __restrict__ dtm2,
    const float* __restrict__ g1w, const float* __restrict__ g1b,
    const float* __restrict__ g2w, const float* __restrict__ g2b)
{
    extern __shared__ float smem[];
    int tid = threadIdx.x;
    int lane = tid & 31, wid = tid >> 5;

    if (blockIdx.x < 4096) {
        // =================== CONV PATH ===================
        float* xs = smem;                 // 11 rows x 32 (col idx = gc+1)
        float* h1 = smem + XS_FL;         // [lr 0..8][cp 0..29][c], stride 36

        int b = blockIdx.x >> 2;
        int base = 7 * (blockIdx.x & 3);  // output row base: 0,7,14,21

        for (int i = tid; i < XS_FL; i += 288) {
            int r = i >> 5, c = i & 31;
            int gr = base - 2 + r, gc = c - 1;
            float v = 0.0f;
            if (gr >= 0 && gr < 28 && gc >= 0 && gc < 28)
                v = x[b * 784 + gr * 28 + gc];
            xs[i] = v;
        }
        for (int i = tid; i < 9 * 2 * 32; i += 288) {
            int lr = i >> 6;
            int cp = ((i >> 5) & 1) ? 29 : 0;
            int c = i & 31;
            h1[(lr * 30 + cp) * 36 + c] = 0.0f;
        }
        __syncthreads();

        // ---- conv1: lane = channel, warp = h1 local row (9 warps, 9 rows)
        {
            int c = lane;
            float wk[9];
            #pragma unroll
            for (int k = 0; k < 9; k++) wk[k] = w1[k * 32 + c];
            float bc = b1[c];

            int lr = wid;                        // 0..8
            int gr = base - 1 + lr;
            float* hrow = h1 + (lr * 30 + 1) * 36 + c;
            if (gr < 0 || gr >= 28) {
                #pragma unroll
                for (int col = 0; col < 28; col++) hrow[col * 36] = 0.0f;
            } else {
                const float* xr = xs + lr * 32;  // x rows lr, lr+1, lr+2
                float a0 = xr[0],   b0 = xr[1];
                float a1v = xr[32], b1v = xr[33];
                float a2v = xr[64], b2v = xr[65];
                #pragma unroll
                for (int col = 0; col < 28; col++) {
                    float c0  = xr[col + 2];
                    float c1v = xr[32 + col + 2];
                    float c2v = xr[64 + col + 2];
                    float t0 = bc;
                    t0 += a0  * wk[0]; t0 += b0  * wk[1]; t0 += c0  * wk[2];
                    float t1 = a1v * wk[3];
                    t1 += b1v * wk[4]; t1 += c1v * wk[5];
                    float t2 = a2v * wk[6];
                    t2 += b2v * wk[7]; t2 += c2v * wk[8];
                    hrow[col * 36] = fmaxf((t0 + t1) + t2, 0.0f);
                    a0 = b0;   b0 = c0;
                    a1v = b1v; b1v = c1v;
                    a2v = b2v; b2v = c2v;
                }
            }
        }
        __syncthreads();

        // ---- G-pass + in-warp channel sum: lane = channel, warp = out row
        if (wid < 7) {
            int c = lane, r = wid;
            float wk[9];
            #pragma unroll
            for (int k = 0; k < 9; k++) wk[k] = w2[k * 32 + c];
            float b2v = b2[0];
            const float* h0 = h1 + ((r    ) * 30) * 36 + c;
            const float* hm = h1 + ((r + 1) * 30) * 36 + c;
            const float* h2 = h1 + ((r + 2) * 30) * 36 + c;
            float a0 = h0[0],  b0 = h0[36];
            float a1 = hm[0],  b1v = hm[36];
            float a2 = h2[0],  b2w = h2[36];
            float* zrow = z_buf + b * ZDIM + (base + r) * 28;
            #pragma unroll
            for (int col = 0; col < 28; col++) {
                float c0 = h0[(col + 2) * 36];
                float c1 = hm[(col + 2) * 36];
                float c2 = h2[(col + 2) * 36];
                float t0 = a0  * wk[0];
                t0 += b0  * wk[1]; t0 += c0 * wk[2];
                float t1 = a1  * wk[3];
                t1 += b1v * wk[4]; t1 += c1 * wk[5];
                float t2 = a2  * wk[6];
                t2 += b2w * wk[7]; t2 += c2 * wk[8];
                float t = (t0 + t1) + t2;
                // cross-lane (channel) sum
                t += __shfl_xor_sync(~0u, t, 16);
                t += __shfl_xor_sync(~0u, t, 8);
                t += __shfl_xor_sync(~0u, t, 4);
                t += __shfl_xor_sync(~0u, t, 2);
                t += __shfl_xor_sync(~0u, t, 1);
                if (lane == 0)
                    zrow[col] = fmaxf(t + b2v, 0.0f);
                a0 = b0;   b0 = c0;
                a1 = b1v;  b1v = c1;
                a2 = b2w;  b2w = c2;
            }
        }
        return;
    }

    // =================== TDA PATH ===================
    {
        int b = blockIdx.x - 4096;
        float* red  = smem;            // 9 warps x 6
        float* fin  = smem + 64;       // 6
        float* lam1 = smem + 80;       // 64
        float* lam2 = smem + 144;      // 64

        const float4* v1 = (const float4*)(dtm1 + b * PIX);
        const float4* v2 = (const float4*)(dtm2 + b * PIX);

        float mx1 = -1e30f, a1 = 1e30f, a2 = 1e30f;
        float mx2 = -1e30f, c1 = 1e30f, c2 = 1e30f;
        if (tid < 196) {
            float4 u4 = v1[tid];
            float4 w4 = v2[tid];
            #pragma unroll
            for (int j = 0; j < 4; j++) {
                float u = (j == 0) ? u4.x : (j == 1) ? u4.y : (j == 2) ? u4.z : u4.w;
                mx1 = fmaxf(mx1, u);
                if (u < a1) { a2 = a1; a1 = u; } else if (u < a2) a2 = u;
                float w = (j == 0) ? w4.x : (j == 1) ? w4.y : (j == 2) ? w4.z : w4.w;
                mx2 = fmaxf(mx2, w);
                if (w < c1) { c2 = c1; c1 = w; } else if (w < c2) c2 = w;
            }
        }
        #pragma unroll
        for (int off = 16; off; off >>= 1) {
            mx1 = fmaxf(mx1, __shfl_xor_sync(~0u, mx1, off));
            float o1 = __shfl_xor_sync(~0u, a1, off);
            float o2 = __shfl_xor_sync(~0u, a2, off);
            float n1 = fminf(a1, o1);
            float n2 = fminf(fmaxf(a1, o1), fminf(a2, o2));
            a1 = n1; a2 = n2;
            mx2 = fmaxf(mx2, __shfl_xor_sync(~0u, mx2, off));
            float p1 = __shfl_xor_sync(~0u, c1, off);
            float p2 = __shfl_xor_sync(~0u, c2, off);
            float q1 = fminf(c1, p1);
            float q2 = fminf(fmaxf(c1, p1), fminf(c2, p2));
            c1 = q1; c2 = q2;
        }
        if (lane == 0) {
            red[wid * 6 + 0] = mx1; red[wid * 6 + 1] = a1; red[wid * 6 + 2] = a2;
            red[wid * 6 + 3] = mx2; red[wid * 6 + 4] = c1; red[wid * 6 + 5] = c2;
        }
        __syncthreads();
        if (tid == 0) {
            float M1 = red[0], A1 = red[1], A2 = red[2];
            float M2 = red[3], C1 = red[4], C2 = red[5];
            #pragma unroll
            for (int w = 1; w < 9; w++) {
                M1 = fmaxf(M1, red[w * 6 + 0]);
                float o1 = red[w * 6 + 1], o2 = red[w * 6 + 2];
                float n1 = fminf(A1, o1);
                float n2 = fminf(fmaxf(A1, o1), fminf(A2, o2));
                A1 = n1; A2 = n2;
                M2 = fmaxf(M2, red[w * 6 + 3]);
                float p1 = red[w * 6 + 4], p2 = red[w * 6 + 5];
                float q1 = fminf(C1, p1);
                float q2 = fminf(fmaxf(C1, p1), fminf(C2, p2));
                C1 = q1; C2 = q2;
            }
            fin[0] = M1; fin[1] = A1; fin[2] = A2;
            fin[3] = M2; fin[4] = C1; fin[5] = C2;
        }
        __syncthreads();

        if (tid < 128) {
            int k = (tid >> 5) & 1, t = tid & 31;
            if (tid < 64) {
                float tv1 = 0.01f + (float)t * (0.28f / 31.0f);
                float m1 = k ? fin[2] : fin[1];
                lam1[tid] = fmaxf(0.0f, fminf(tv1 - m1, fin[0] - tv1));
            } else {
                float tv2 = 0.05f + (float)t * (0.25f / 31.0f);
                float m2 = k ? fin[5] : fin[4];
                lam2[tid - 64] = fmaxf(0.0f, fminf(tv2 - m2, fin[3] - tv2));
            }
        }
        __syncthreads();

        if (tid < 32) {
            float acc = g1b[tid];
            #pragma unroll
            for (int i = 0; i < 64; i++) acc += lam1[i] * g1w[i * 32 + tid];
            z_buf[b * ZDIM + 784 + tid] = fmaxf(acc, 0.0f);
        } else if (tid < 64) {
            int j = tid - 32;
            float acc = g2b[j];
            #pragma unroll
            for (int i = 0; i < 64; i++) acc += lam2[i] * g2w[i * 32 + j];
            z_buf[b * ZDIM + 816 + j] = fmaxf(acc, 0.0f);
        }
    }
}

// ---------------------------------------------------------------------------
// MLP head v4 (R13 version, restored): GEMM-style, 4 samples/block, grid 256,
// depth-4 weight prefetch ring.
// ---------------------------------------------------------------------------
#define ZT_FL   (ZDIM * 4)
#define PART_FL (256 * 17)
#define YS_FL   (4 * 68)
#define MSMEM_FLOATS (ZT_FL + PART_FL + YS_FL)

__global__ void __launch_bounds__(256) mlp_kernel(
    const float* __restrict__ fc1w, const float* __restrict__ fc1b,
    const float* __restrict__ fc2w, const float* __restrict__ fc2b,
    float* __restrict__ out)
{
    extern __shared__ float msmem[];
    float* zt   = msmem;                 // [row][s], stride 4 (16B aligned)
    float* part = msmem + ZT_FL;         // [(s*64+c)*17 + seg]
    float* ys   = part + PART_FL;        // [s][68]

    int tid = threadIdx.x;
    int bbase = blockIdx.x * 4;

    {
        const float4* zb4 = (const float4*)(z_buf + (size_t)bbase * ZDIM);
        for (int i = tid; i < 4 * (ZDIM / 4); i += 256) {
            int s = i / (ZDIM / 4);
            int r4 = i - s * (ZDIM / 4);
            float4 v = zb4[i];
            int r = r4 * 4;
            zt[(r + 0) * 4 + s] = v.x;
            zt[(r + 1) * 4 + s] = v.y;
            zt[(r + 2) * 4 + s] = v.z;
            zt[(r + 3) * 4 + s] = v.w;
        }
    }
    __syncthreads();

    {
        int seg = tid >> 4, cg = tid & 15;
        int r0 = seg * 53;
        const float4* wrow = (const float4*)fc1w + cg;   // + row*16

        float acc[4][4];
        #pragma unroll
        for (int s = 0; s < 4; s++)
            #pragma unroll
            for (int c = 0; c < 4; c++) acc[s][c] = 0.0f;

        float4 wb[4];
        #pragma unroll
        for (int g = 0; g < 4; g++) wb[g] = wrow[(r0 + g) * 16];
        float4 wlast = wrow[(r0 + 52) * 16];

        #pragma unroll 1
        for (int it = 0; it < 12; it++) {          // rows r0 .. r0+47
            int rb = r0 + it * 4;
            #pragma unroll
            for (int g = 0; g < 4; g++) {
                float4 w = wb[g];
                wb[g] = wrow[(rb + g + 4) * 16];   // prefetch rows +4..+51
                float4 zv = *(const float4*)(zt + (rb + g) * 4);
                acc[0][0] += zv.x * w.x; acc[0][1] += zv.x * w.y;
                acc[0][2] += zv.x * w.z; acc[0][3] += zv.x * w.w;
                acc[1][0] += zv.y * w.x; acc[1][1] += zv.y * w.y;
                acc[1][2] += zv.y * w.z; acc[1][3] += zv.y * w.w;
                acc[2][0] += zv.z * w.x; acc[2][1] += zv.z * w.y;
                acc[2][2] += zv.z * w.z; acc[2][3] += zv.z * w.w;
                acc[3][0] += zv.w * w.x; acc[3][1] += zv.w * w.y;
                acc[3][2] += zv.w * w.z; acc[3][3] += zv.w * w.w;
            }
        }
        #pragma unroll
        for (int g = 0; g < 5; g++) {
            float4 w = (g < 4) ? wb[g] : wlast;
            float4 zv = *(const float4*)(zt + (r0 + 48 + g) * 4);
            acc[0][0] += zv.x * w.x; acc[0][1] += zv.x * w.y;
            acc[0][2] += zv.x * w.z; acc[0][3] += zv.x * w.w;
            acc[1][0] += zv.y * w.x; acc[1][1] += zv.y * w.y;
            acc[1][2] += zv.y * w.z; acc[1][3] += zv.y * w.w;
            acc[2][0] += zv.z * w.x; acc[2][1] += zv.z * w.y;
            acc[2][2] += zv.z * w.z; acc[2][3] += zv.z * w.w;
            acc[3][0] += zv.w * w.x; acc[3][1] += zv.w * w.y;
            acc[3][2] += zv.w * w.z; acc[3][3] += zv.w * w.w;
        }

        #pragma unroll
        for (int s = 0; s < 4; s++)
            #pragma unroll
            for (int c = 0; c < 4; c++)
                part[(s * 64 + cg * 4 + c) * 17 + seg] = acc[s][c];
    }
    __syncthreads();

    {
        int o = tid;                    // s = o>>6, c = o&63
        const float* pp = part + o * 17;
        float s0 = 0.0f, s1 = 0.0f, s2 = 0.0f, s3 = 0.0f;
        #pragma unroll
        for (int g = 0; g < 4; g++) {
            s0 += pp[4 * g + 0];
            s1 += pp[4 * g + 1];
            s2 += pp[4 * g + 2];
            s3 += pp[4 * g + 3];
        }
        int s = o >> 6, c = o & 63;
        ys[s * 68 + c] = fmaxf((s0 + s1) + (s2 + s3) + fc1b[c], 0.0f);
    }
    __syncthreads();

    if (tid < 40) {
        int s = tid / 10, k = tid - s * 10;
        float acc = fc2b[k];
        #pragma unroll
        for (int jj = 0; jj < 64; jj++)
            acc += ys[s * 68 + jj] * fc2w[jj * 10 + k];
        out[(bbase + s) * 10 + k] = acc;
    }
}

// ---------------------------------------------------------------------------
extern "C" void kernel_launch(void* const* d_in, const int* in_sizes, int n_in,
                              void* d_out, int out_size)
{
    const float* x    = (const float*)d_in[0];
    const float* dtm1 = (const float*)d_in[1];
    const float* dtm2 = (const float*)d_in[2];
    const float* w1   = (const float*)d_in[3];
    const float* b1   = (const float*)d_in[4];
    const float* w2   = (const float*)d_in[5];
    const float* b2   = (const float*)d_in[6];
    const float* g1w  = (const float*)d_in[7];
    const float* g1b  = (const float*)d_in[8];
    const float* g2w  = (const float*)d_in[9];
    const float* g2b  = (const float*)d_in[10];
    const float* fc1w = (const float*)d_in[11];
    const float* fc1b = (const float*)d_in[12];
    const float* fc2w = (const float*)d_in[13];
    const float* fc2b = (const float*)d_in[14];
    float* out = (float*)d_out;

    cudaFuncSetAttribute(fused_kernel, cudaFuncAttributeMaxDynamicSharedMemorySize,
                         CSMEM_FLOATS * (int)sizeof(float));
    cudaFuncSetAttribute(fused_kernel, cudaFuncAttributePreferredSharedMemoryCarveout,
                         100);
    cudaFuncSetAttribute(mlp_kernel, cudaFuncAttributeMaxDynamicSharedMemorySize,
                         MSMEM_FLOATS * (int)sizeof(float));

    fused_kernel<<<4096 + NB, 288, CSMEM_FLOATS * sizeof(float)>>>(
        x, w1, b1, w2, b2, dtm1, dtm2, g1w, g1b, g2w, g2b);
    mlp_kernel<<<NB / 4, 256, MSMEM_FLOATS * sizeof(float)>>>(
        fc1w, fc1b, fc2w, fc2b, out);
}